// round 11
// baseline (speedup 1.0000x reference)
#include <cuda_runtime.h>
#include <cuda_fp16.h>
#include <cstdint>

// SupConLoss: features [4096,2,128] f32, labels [4096] int(32|64) -> scalar f32
// N=8192. S[i,j]=dot(u'_i,u'_j), u' = normalized * (1/sqrt T).
// pass A (mma.sync fp16 hi/lo, 512 thr): upper-tri 128x128 tiles; ns via symmetry.
// build: per-class ordered row lists. pass B: positive pairs, fp32 recompute.

#define NROWS 8192
#define BQ    4096
#define NCLS  100
#define RSQRT_T 3.77964473009227f   // 1/sqrt(0.07)

__device__ float  g_u [NROWS * 128];
__device__ __half g_uh[NROWS * 128];
__device__ __half g_ul[NROWS * 128];
__device__ int    g_lab[NROWS];
__device__ float  g_negsum[NROWS];
__device__ float  g_loss;
__device__ int    g_is64;

#define LCAP  640
__device__ int    g_list[NCLS * LCAP];
__device__ int    g_cnt[NCLS];

__device__ __forceinline__ uint32_t smem_u32(const void* p) {
    uint32_t a;
    asm("{ .reg .u64 t; cvta.to.shared.u64 t, %1; cvt.u32.u64 %0, t; }" : "=r"(a) : "l"(p));
    return a;
}

#define CP_ASYNC16(dst, src) \
    asm volatile("cp.async.ca.shared.global [%0], [%1], 16;" \
        :: "r"((uint32_t)(dst)), "l"(__cvta_generic_to_global((const void*)(src))) : "memory")
#define CP_ASYNC_COMMIT() asm volatile("cp.async.commit_group;" ::: "memory")
#define CP_ASYNC_WAIT_ALL() asm volatile("cp.async.wait_all;" ::: "memory")

#define LDSM_X4(R, addr) \
    asm volatile("ldmatrix.sync.aligned.m8n8.x4.shared.b16 {%0,%1,%2,%3}, [%4];" \
        : "=r"((R)[0]), "=r"((R)[1]), "=r"((R)[2]), "=r"((R)[3]) : "r"(addr))

#define MMA16816(D, A, B0, B1) \
    asm volatile("mma.sync.aligned.m16n8k16.row.col.f32.f16.f16.f32 " \
        "{%0,%1,%2,%3}, {%4,%5,%6,%7}, {%8,%9}, {%0,%1,%2,%3};" \
        : "+f"((D)[0]), "+f"((D)[1]), "+f"((D)[2]), "+f"((D)[3]) \
        : "r"((A)[0]), "r"((A)[1]), "r"((A)[2]), "r"((A)[3]), "r"(B0), "r"(B1))

// ---------------------------------------------------------------- detect int64/int32
__global__ void detect_kernel(const int* __restrict__ Li) {
    __shared__ int nz;
    if (threadIdx.x == 0) nz = 0;
    __syncthreads();
    for (int i = threadIdx.x; i < 2048; i += blockDim.x)
        if (Li[2 * i + 1] != 0) nz = 1;
    __syncthreads();
    if (threadIdx.x == 0) g_is64 = (nz == 0);
}

// ---------------------------------------------------------------- normalize + split
__global__ void norm_kernel(const float* __restrict__ F, const int* __restrict__ Li) {
    int i = blockIdx.x, d = threadIdx.x;
    int b = i & (BQ - 1), v = i >> 12;
    float f = F[b * 256 + v * 128 + d];

    float ss = f * f;
    #pragma unroll
    for (int off = 16; off > 0; off >>= 1)
        ss += __shfl_xor_sync(0xffffffffu, ss, off);
    __shared__ float w[4];
    int lane = d & 31, warp = d >> 5;
    if (lane == 0) w[warp] = ss;
    __syncthreads();
    float s = rsqrtf(w[0] + w[1] + w[2] + w[3]) * RSQRT_T;

    float u = f * s;
    __half h = __float2half_rn(u);
    g_u [i * 128 + d] = u;
    g_uh[i * 128 + d] = h;
    g_ul[i * 128 + d] = __float2half_rn(u - __half2float(h));

    if (d == 0) {
        g_lab[i]    = g_is64 ? Li[2 * b] : Li[b];
        g_negsum[i] = 0.f;
        if (i == 0) g_loss = 0.f;
    }
}

// ---------------------------------------------------------------- build class lists
__global__ void build_kernel() {
    __shared__ int cnts[256];
    const int cls = blockIdx.x, tid = threadIdx.x;

    int base = tid * 32, cnt = 0;
    #pragma unroll
    for (int k = 0; k < 32; k++) cnt += (g_lab[base + k] == cls);
    cnts[tid] = cnt;
    __syncthreads();
    #pragma unroll
    for (int dd = 1; dd < 256; dd <<= 1) {
        int v = cnts[tid];
        int a = (tid >= dd) ? cnts[tid - dd] : 0;
        __syncthreads();
        cnts[tid] = v + a;
        __syncthreads();
    }
    if (tid == 255) g_cnt[cls] = (cnts[255] > LCAP) ? LCAP : cnts[255];
    int off = cnts[tid] - cnt;
    #pragma unroll
    for (int k = 0; k < 32; k++)
        if (g_lab[base + k] == cls && off < LCAP) g_list[cls * LCAP + off++] = base + k;
}

// ---------------------------------------------------------------- pass A (512 threads)
#define PAN   34816u                 // 128*272
#define O_AHI 0u
#define O_ALO 34816u
#define O_BHI 69632u
#define O_BLO 104448u
#define O_LAB 139264u
#define O_RED 140288u
#define PASSA_SMEM 141312

__global__ __launch_bounds__(512, 1) void passA_kernel() {
    extern __shared__ char sm[];
    const uint32_t sa = smem_u32(sm);
    const int tid = threadIdx.x, wid = tid >> 5, lane = tid & 31;

    // upper-triangle tile index (64x64 tiles)
    int rem = blockIdx.x, ti = 0;
    while (rem >= 64 - ti) { rem -= 64 - ti; ti++; }
    const int tj = ti + rem;
    const int i0 = ti * 128, j0 = tj * 128;
    const bool diag = (ti == tj);

    int*   li_s  = (int*)(sm + O_LAB);
    int*   lj_s  = li_s + 128;
    float* s_row = (float*)(sm + O_RED);
    float* s_col = s_row + 128;

    if (tid < 256) ((float*)(sm + O_RED))[tid] = 0.f;
    if (tid < 128) { li_s[tid] = g_lab[i0 + tid]; lj_s[tid] = g_lab[j0 + tid]; }

    // async panel fill
    const int nPan = diag ? 2 : 4;
    for (int pan = 0; pan < nPan; pan++) {
        const __half* src = (pan & 1) ? g_ul : g_uh;
        const int rbase = (pan < 2) ? i0 : j0;
        const uint32_t dst = sa + pan * PAN;
        #pragma unroll
        for (int t = 0; t < 4; t++) {
            int f = tid + t * 512;
            int r = f >> 4, c = f & 15;
            CP_ASYNC16(dst + r * 272 + c * 16,
                       (const char*)(src + (rbase + r) * 128) + c * 16);
        }
    }
    CP_ASYNC_COMMIT();
    CP_ASYNC_WAIT_ALL();
    __syncthreads();

    // 16 warps: 4x4 grid, each warp 32x32 output
    const int wm = (wid >> 2) * 32;
    const int wn = (wid & 3) * 32;
    const int lrow = (lane & 7) + ((lane >> 3) & 1) * 8;
    const int lk   = (lane >> 4) * 8;

    uint32_t aOff[3] = { O_AHI, O_AHI, O_ALO };
    uint32_t bOff[3] = { diag ? O_AHI : O_BHI, diag ? O_ALO : O_BLO, diag ? O_AHI : O_BHI };

    float d[2][4][4];
    #pragma unroll
    for (int a = 0; a < 2; a++)
        #pragma unroll
        for (int b = 0; b < 4; b++)
            #pragma unroll
            for (int c = 0; c < 4; c++) d[a][b][c] = 0.f;

    #pragma unroll 1
    for (int ch = 0; ch < 24; ch++) {
        const int t = ch >> 3, kk = (ch & 7) * 16;
        const uint32_t abase = sa + aOff[t] + (kk + lk) * 2;
        const uint32_t bbase = sa + bOff[t] + (kk + lk) * 2;

        uint32_t A[2][4], B[2][4];
        #pragma unroll
        for (int ma = 0; ma < 2; ma++)
            LDSM_X4(A[ma], abase + (wm + ma * 16 + lrow) * 272);
        #pragma unroll
        for (int g = 0; g < 2; g++)
            LDSM_X4(B[g], bbase + (wn + g * 16 + lrow) * 272);

        #pragma unroll
        for (int ma = 0; ma < 2; ma++)
            #pragma unroll
            for (int nb = 0; nb < 4; nb++) {
                const int g = nb >> 1, h = nb & 1;
                MMA16816(d[ma][nb], A[ma], B[g][h], B[g][h + 2]);
            }
    }

    // ---- fused epilogue ----
    const int grp = lane >> 2, q = lane & 3;
    float rs[2][2];
    rs[0][0] = rs[0][1] = rs[1][0] = rs[1][1] = 0.f;
    float cs[4][2];
    #pragma unroll
    for (int nb = 0; nb < 4; nb++) cs[nb][0] = cs[nb][1] = 0.f;

    #pragma unroll
    for (int ma = 0; ma < 2; ma++) {
        const int r0 = wm + ma * 16 + grp, r1 = r0 + 8;
        const int l0 = li_s[r0], l1 = li_s[r1];
        #pragma unroll
        for (int nb = 0; nb < 4; nb++) {
            const int c0 = wn + nb * 8 + q * 2;
            const int lc0 = lj_s[c0], lc1 = lj_s[c0 + 1];
            float v00 = (l0 != lc0) ? __expf(d[ma][nb][0]) : 0.f;
            float v01 = (l0 != lc1) ? __expf(d[ma][nb][1]) : 0.f;
            float v10 = (l1 != lc0) ? __expf(d[ma][nb][2]) : 0.f;
            float v11 = (l1 != lc1) ? __expf(d[ma][nb][3]) : 0.f;
            rs[ma][0] += v00 + v01;
            rs[ma][1] += v10 + v11;
            cs[nb][0] += v00 + v10;
            cs[nb][1] += v01 + v11;
        }
    }

    #pragma unroll
    for (int o = 1; o <= 2; o <<= 1) {
        #pragma unroll
        for (int ma = 0; ma < 2; ma++) {
            rs[ma][0] += __shfl_xor_sync(0xffffffffu, rs[ma][0], o);
            rs[ma][1] += __shfl_xor_sync(0xffffffffu, rs[ma][1], o);
        }
    }
    if (q == 0) {
        #pragma unroll
        for (int ma = 0; ma < 2; ma++) {
            atomicAdd(&s_row[wm + ma * 16 + grp],     rs[ma][0]);
            atomicAdd(&s_row[wm + ma * 16 + grp + 8], rs[ma][1]);
        }
    }

    #pragma unroll
    for (int o = 4; o <= 16; o <<= 1)
        #pragma unroll
        for (int nb = 0; nb < 4; nb++) {
            cs[nb][0] += __shfl_xor_sync(0xffffffffu, cs[nb][0], o);
            cs[nb][1] += __shfl_xor_sync(0xffffffffu, cs[nb][1], o);
        }
    if (grp == 0) {
        #pragma unroll
        for (int nb = 0; nb < 4; nb++) {
            atomicAdd(&s_col[wn + nb * 8 + q * 2],     cs[nb][0]);
            atomicAdd(&s_col[wn + nb * 8 + q * 2 + 1], cs[nb][1]);
        }
    }
    __syncthreads();

    if (tid < 128) {
        atomicAdd(&g_negsum[j0 + tid], s_col[tid]);
        if (!diag) atomicAdd(&g_negsum[i0 + tid], s_row[tid]);
    }
}

// ---------------------------------------------------------------- pass B: positive pairs
#define NSLOT 15
#define CH    64
#define PB_STRIDE 68
#define PASSB_SMEM (2 * 128 * PB_STRIDE * 4 + 64)

__global__ __launch_bounds__(256, 3) void passB_kernel() {
    extern __shared__ char smB[];
    float* uA  = (float*)smB;
    float* uB  = uA + 128 * PB_STRIDE;
    float* red = uB + 128 * PB_STRIDE;

    const int cls  = blockIdx.x / NSLOT;
    const int slot = blockIdx.x % NSLOT;
    const int tid  = threadIdx.x;

    const int n = g_cnt[cls];
    if (n < 2) return;
    const int nch = (n + CH - 1) / CH;
    const int npairs = nch * (nch + 1) / 2;
    if (slot >= npairs) return;

    const int* list = g_list + cls * LCAP;
    const int tx = tid & 15, ty = tid >> 4;
    float blocksum = 0.f;

    for (int pp = slot; pp < npairs; pp += NSLOT) {
        int p = 0, rm = pp;
        while (rm >= nch - p) { rm -= nch - p; p++; }
        const int q = p + rm;

        for (int e = tid; e < CH * 32; e += 256) {
            int r = e >> 5, seg = e & 31;
            float4 wa = make_float4(0.f, 0.f, 0.f, 0.f), wb = wa;
            if (p * CH + r < n) wa = *(const float4*)(g_u + list[p * CH + r] * 128 + seg * 4);
            if (q * CH + r < n) wb = *(const float4*)(g_u + list[q * CH + r] * 128 + seg * 4);
            int d0 = seg * 4;
            uA[(d0 + 0) * PB_STRIDE + r] = wa.x; uA[(d0 + 1) * PB_STRIDE + r] = wa.y;
            uA[(d0 + 2) * PB_STRIDE + r] = wa.z; uA[(d0 + 3) * PB_STRIDE + r] = wa.w;
            uB[(d0 + 0) * PB_STRIDE + r] = wb.x; uB[(d0 + 1) * PB_STRIDE + r] = wb.y;
            uB[(d0 + 2) * PB_STRIDE + r] = wb.z; uB[(d0 + 3) * PB_STRIDE + r] = wb.w;
        }
        __syncthreads();

        float acc[4][4];
        #pragma unroll
        for (int a = 0; a < 4; a++)
            #pragma unroll
            for (int b = 0; b < 4; b++) acc[a][b] = 0.f;

        #pragma unroll 4
        for (int k = 0; k < 128; k++) {
            float ra[4], rb[4];
            *(float4*)ra = *(float4*)&uA[k * PB_STRIDE + tx * 4];
            *(float4*)rb = *(float4*)&uB[k * PB_STRIDE + ty * 4];
            #pragma unroll
            for (int a = 0; a < 4; a++)
                #pragma unroll
                for (int b = 0; b < 4; b++)
                    acc[a][b] = fmaf(ra[a], rb[b], acc[a][b]);
        }

        #pragma unroll
        for (int a = 0; a < 4; a++) {
            int X = p * CH + tx * 4 + a;
            #pragma unroll
            for (int b = 0; b < 4; b++) {
                int Y = q * CH + ty * 4 + b;
                if (X < n && Y < n && (p < q || X < Y)) {
                    float S = acc[a][b];
                    float e = __expf(S);
                    blocksum += 2.f * S - __logf(g_negsum[list[Y]] + e)
                                        - __logf(g_negsum[list[X]] + e);
                }
            }
        }
        __syncthreads();
    }

    float tot = blocksum;
    #pragma unroll
    for (int o = 16; o > 0; o >>= 1)
        tot += __shfl_xor_sync(0xffffffffu, tot, o);
    if ((tid & 31) == 0) red[tid >> 5] = tot;
    __syncthreads();
    if (tid == 0) {
        float s = 0.f;
        #pragma unroll
        for (int w = 0; w < 8; w++) s += red[w];
        atomicAdd(&g_loss, s);
    }
}

__global__ void fin_kernel(float* __restrict__ out) {
    out[0] = -g_loss / (float)NROWS;
}

// ----------------------------------------------------------------
extern "C" void kernel_launch(void* const* d_in, const int* in_sizes, int n_in,
                              void* d_out, int out_size) {
    const float* F  = (const float*)d_in[0];
    const int*   Li = (const int*)d_in[1];

    cudaFuncSetAttribute(passA_kernel, cudaFuncAttributeMaxDynamicSharedMemorySize, PASSA_SMEM);
    cudaFuncSetAttribute(passB_kernel, cudaFuncAttributeMaxDynamicSharedMemorySize, PASSB_SMEM);

    detect_kernel<<<1, 256>>>(Li);
    norm_kernel<<<NROWS, 128>>>(F, Li);
    build_kernel<<<NCLS, 256>>>();
    passA_kernel<<<2080, 512, PASSA_SMEM>>>();
    passB_kernel<<<NCLS * NSLOT, 256, PASSB_SMEM>>>();
    fin_kernel<<<1, 1>>>((float*)d_out);
}

// round 12
// speedup vs baseline: 1.6170x; 1.6170x over previous
#include <cuda_runtime.h>
#include <cuda_fp16.h>
#include <cstdint>

// SupConLoss: features [4096,2,128] f32, labels [4096] int(32|64) -> scalar f32
// N=8192. S[i,j]=dot(u'_i,u'_j), u' = normalized * (1/sqrt T).
// pass A (mma.sync fp16 hi/lo, 256 thr, prefetch-pipelined): upper-tri 128x128 tiles.
// build: per-class ordered row lists. pass B: positive pairs, fp32 recompute.

#define NROWS 8192
#define BQ    4096
#define NCLS  100
#define RSQRT_T 3.77964473009227f   // 1/sqrt(0.07)

__device__ float  g_u [NROWS * 128];
__device__ __half g_uh[NROWS * 128];
__device__ __half g_ul[NROWS * 128];
__device__ int    g_lab[NROWS];
__device__ float  g_negsum[NROWS];
__device__ float  g_loss;
__device__ int    g_is64;

#define LCAP  640
__device__ int    g_list[NCLS * LCAP];
__device__ int    g_cnt[NCLS];

__device__ __forceinline__ uint32_t smem_u32(const void* p) {
    uint32_t a;
    asm("{ .reg .u64 t; cvta.to.shared.u64 t, %1; cvt.u32.u64 %0, t; }" : "=r"(a) : "l"(p));
    return a;
}

#define CP_ASYNC16(dst, src) \
    asm volatile("cp.async.ca.shared.global [%0], [%1], 16;" \
        :: "r"((uint32_t)(dst)), "l"(__cvta_generic_to_global((const void*)(src))) : "memory")
#define CP_ASYNC_COMMIT() asm volatile("cp.async.commit_group;" ::: "memory")
#define CP_ASYNC_WAIT_ALL() asm volatile("cp.async.wait_all;" ::: "memory")

#define LDSM_X4(R, addr) \
    asm volatile("ldmatrix.sync.aligned.m8n8.x4.shared.b16 {%0,%1,%2,%3}, [%4];" \
        : "=r"((R)[0]), "=r"((R)[1]), "=r"((R)[2]), "=r"((R)[3]) : "r"(addr))

#define MMA16816(D, A, B0, B1) \
    asm volatile("mma.sync.aligned.m16n8k16.row.col.f32.f16.f16.f32 " \
        "{%0,%1,%2,%3}, {%4,%5,%6,%7}, {%8,%9}, {%0,%1,%2,%3};" \
        : "+f"((D)[0]), "+f"((D)[1]), "+f"((D)[2]), "+f"((D)[3]) \
        : "r"((A)[0]), "r"((A)[1]), "r"((A)[2]), "r"((A)[3]), "r"(B0), "r"(B1))

// ---------------------------------------------------------------- detect int64/int32
__global__ void detect_kernel(const int* __restrict__ Li) {
    __shared__ int nz;
    if (threadIdx.x == 0) nz = 0;
    __syncthreads();
    for (int i = threadIdx.x; i < 2048; i += blockDim.x)
        if (Li[2 * i + 1] != 0) nz = 1;
    __syncthreads();
    if (threadIdx.x == 0) g_is64 = (nz == 0);
}

// ---------------------------------------------------------------- normalize + split
__global__ void norm_kernel(const float* __restrict__ F, const int* __restrict__ Li) {
    int i = blockIdx.x, d = threadIdx.x;
    int b = i & (BQ - 1), v = i >> 12;
    float f = F[b * 256 + v * 128 + d];

    float ss = f * f;
    #pragma unroll
    for (int off = 16; off > 0; off >>= 1)
        ss += __shfl_xor_sync(0xffffffffu, ss, off);
    __shared__ float w[4];
    int lane = d & 31, warp = d >> 5;
    if (lane == 0) w[warp] = ss;
    __syncthreads();
    float s = rsqrtf(w[0] + w[1] + w[2] + w[3]) * RSQRT_T;

    float u = f * s;
    __half h = __float2half_rn(u);
    g_u [i * 128 + d] = u;
    g_uh[i * 128 + d] = h;
    g_ul[i * 128 + d] = __float2half_rn(u - __half2float(h));

    if (d == 0) {
        g_lab[i]    = g_is64 ? Li[2 * b] : Li[b];
        g_negsum[i] = 0.f;
        if (i == 0) g_loss = 0.f;
    }
}

// ---------------------------------------------------------------- build class lists
__global__ void build_kernel() {
    __shared__ int cnts[256];
    const int cls = blockIdx.x, tid = threadIdx.x;

    int base = tid * 32, cnt = 0;
    #pragma unroll
    for (int k = 0; k < 32; k++) cnt += (g_lab[base + k] == cls);
    cnts[tid] = cnt;
    __syncthreads();
    #pragma unroll
    for (int dd = 1; dd < 256; dd <<= 1) {
        int v = cnts[tid];
        int a = (tid >= dd) ? cnts[tid - dd] : 0;
        __syncthreads();
        cnts[tid] = v + a;
        __syncthreads();
    }
    if (tid == 255) g_cnt[cls] = (cnts[255] > LCAP) ? LCAP : cnts[255];
    int off = cnts[tid] - cnt;
    #pragma unroll
    for (int k = 0; k < 32; k++)
        if (g_lab[base + k] == cls && off < LCAP) g_list[cls * LCAP + off++] = base + k;
}

// ---------------------------------------------------------------- pass A (256 thr, pipelined)
#define PAN   34816u                 // 128*272
#define O_AHI 0u
#define O_ALO 34816u
#define O_BHI 69632u
#define O_BLO 104448u
#define O_LAB 139264u
#define O_RED 140288u
#define PASSA_SMEM 141312

__global__ __launch_bounds__(256, 1) void passA_kernel() {
    extern __shared__ char sm[];
    const uint32_t sa = smem_u32(sm);
    const int tid = threadIdx.x, wid = tid >> 5, lane = tid & 31;

    // upper-triangle tile index (64x64 tiles)
    int rem = blockIdx.x, ti = 0;
    while (rem >= 64 - ti) { rem -= 64 - ti; ti++; }
    const int tj = ti + rem;
    const int i0 = ti * 128, j0 = tj * 128;
    const bool diag = (ti == tj);

    int*   li_s  = (int*)(sm + O_LAB);
    int*   lj_s  = li_s + 128;
    float* s_row = (float*)(sm + O_RED);
    float* s_col = s_row + 128;

    ((float*)(sm + O_RED))[tid] = 0.f;
    if (tid < 128) { li_s[tid] = g_lab[i0 + tid]; lj_s[tid] = g_lab[j0 + tid]; }

    // async panel fill
    const int nPan = diag ? 2 : 4;
    for (int pan = 0; pan < nPan; pan++) {
        const __half* src = (pan & 1) ? g_ul : g_uh;
        const int rbase = (pan < 2) ? i0 : j0;
        const uint32_t dst = sa + pan * PAN;
        #pragma unroll
        for (int t = 0; t < 8; t++) {
            int f = tid + t * 256;
            int r = f >> 4, c = f & 15;
            CP_ASYNC16(dst + r * 272 + c * 16,
                       (const char*)(src + (rbase + r) * 128) + c * 16);
        }
    }
    CP_ASYNC_COMMIT();
    CP_ASYNC_WAIT_ALL();
    __syncthreads();

    // 8 warps: 4x2 grid, each warp 32x64 output
    const int wm = (wid >> 1) * 32;
    const int wn = (wid & 1) * 64;
    const int lrow = (lane & 7) + ((lane >> 3) & 1) * 8;
    const int lk   = (lane >> 4) * 8;

    const uint32_t BH = diag ? O_AHI : O_BHI;
    const uint32_t BL = diag ? O_ALO : O_BLO;

    const uint32_t aRow = sa + (wm + lrow) * 272 + lk * 2;       // + {0,16}*272 + koff + termoff
    const uint32_t bRow = sa + (wn + lrow) * 272 + lk * 2;

    float d[2][8][4];
    #pragma unroll
    for (int a = 0; a < 2; a++)
        #pragma unroll
        for (int b = 0; b < 8; b++)
            #pragma unroll
            for (int c = 0; c < 4; c++) d[a][b][c] = 0.f;

    uint32_t A[2][2][4], B[2][4][4];

    // prologue: chunk 0 (term 0 = hi*hi, kk = 0)
    #pragma unroll
    for (int ma = 0; ma < 2; ma++)
        LDSM_X4(A[0][ma], aRow + O_AHI + ma * 16 * 272);
    #pragma unroll
    for (int g = 0; g < 4; g++)
        LDSM_X4(B[0][g], bRow + BH + g * 16 * 272);

    #pragma unroll 2
    for (int ch = 0; ch < 24; ch++) {
        const int cur = ch & 1, nxt = cur ^ 1;
        if (ch < 23) {
            const int c2 = ch + 1;
            const int t  = c2 >> 3;
            const uint32_t kb = (uint32_t)((c2 & 7) * 32);       // k offset bytes
            const uint32_t ao = (t == 2) ? O_ALO : O_AHI;
            const uint32_t bo = (t == 1) ? BL : BH;
            #pragma unroll
            for (int ma = 0; ma < 2; ma++)
                LDSM_X4(A[nxt][ma], aRow + ao + kb + ma * 16 * 272);
            #pragma unroll
            for (int g = 0; g < 4; g++)
                LDSM_X4(B[nxt][g], bRow + bo + kb + g * 16 * 272);
        }
        #pragma unroll
        for (int ma = 0; ma < 2; ma++)
            #pragma unroll
            for (int nb = 0; nb < 8; nb++) {
                const int g = nb >> 1, h = nb & 1;
                MMA16816(d[ma][nb], A[cur][ma], B[cur][g][h], B[cur][g][h + 2]);
            }
    }

    // ---- fused epilogue: masked exp, row/col sums ----
    const int grp = lane >> 2, q = lane & 3;
    float rs[2][2];
    rs[0][0] = rs[0][1] = rs[1][0] = rs[1][1] = 0.f;
    float cs[8][2];
    #pragma unroll
    for (int nb = 0; nb < 8; nb++) cs[nb][0] = cs[nb][1] = 0.f;

    #pragma unroll
    for (int ma = 0; ma < 2; ma++) {
        const int r0 = wm + ma * 16 + grp, r1 = r0 + 8;
        const int l0 = li_s[r0], l1 = li_s[r1];
        #pragma unroll
        for (int nb = 0; nb < 8; nb++) {
            const int c0 = wn + nb * 8 + q * 2;
            const int lc0 = lj_s[c0], lc1 = lj_s[c0 + 1];
            float v00 = (l0 != lc0) ? __expf(d[ma][nb][0]) : 0.f;
            float v01 = (l0 != lc1) ? __expf(d[ma][nb][1]) : 0.f;
            float v10 = (l1 != lc0) ? __expf(d[ma][nb][2]) : 0.f;
            float v11 = (l1 != lc1) ? __expf(d[ma][nb][3]) : 0.f;
            rs[ma][0] += v00 + v01;
            rs[ma][1] += v10 + v11;
            cs[nb][0] += v00 + v10;
            cs[nb][1] += v01 + v11;
        }
    }

    #pragma unroll
    for (int o = 1; o <= 2; o <<= 1) {
        #pragma unroll
        for (int ma = 0; ma < 2; ma++) {
            rs[ma][0] += __shfl_xor_sync(0xffffffffu, rs[ma][0], o);
            rs[ma][1] += __shfl_xor_sync(0xffffffffu, rs[ma][1], o);
        }
    }
    if (q == 0) {
        #pragma unroll
        for (int ma = 0; ma < 2; ma++) {
            atomicAdd(&s_row[wm + ma * 16 + grp],     rs[ma][0]);
            atomicAdd(&s_row[wm + ma * 16 + grp + 8], rs[ma][1]);
        }
    }

    #pragma unroll
    for (int o = 4; o <= 16; o <<= 1)
        #pragma unroll
        for (int nb = 0; nb < 8; nb++) {
            cs[nb][0] += __shfl_xor_sync(0xffffffffu, cs[nb][0], o);
            cs[nb][1] += __shfl_xor_sync(0xffffffffu, cs[nb][1], o);
        }
    if (grp == 0) {
        #pragma unroll
        for (int nb = 0; nb < 8; nb++) {
            atomicAdd(&s_col[wn + nb * 8 + q * 2],     cs[nb][0]);
            atomicAdd(&s_col[wn + nb * 8 + q * 2 + 1], cs[nb][1]);
        }
    }
    __syncthreads();

    if (tid < 128) {
        atomicAdd(&g_negsum[j0 + tid], s_col[tid]);
        if (!diag) atomicAdd(&g_negsum[i0 + tid], s_row[tid]);
    }
}

// ---------------------------------------------------------------- pass B: positive pairs
#define NSLOT 15
#define CH    64
#define PB_STRIDE 68
#define PASSB_SMEM (2 * 128 * PB_STRIDE * 4 + 64)

__global__ __launch_bounds__(256, 3) void passB_kernel() {
    extern __shared__ char smB[];
    float* uA  = (float*)smB;
    float* uB  = uA + 128 * PB_STRIDE;
    float* red = uB + 128 * PB_STRIDE;

    const int cls  = blockIdx.x / NSLOT;
    const int slot = blockIdx.x % NSLOT;
    const int tid  = threadIdx.x;

    const int n = g_cnt[cls];
    if (n < 2) return;
    const int nch = (n + CH - 1) / CH;
    const int npairs = nch * (nch + 1) / 2;
    if (slot >= npairs) return;

    const int* list = g_list + cls * LCAP;
    const int tx = tid & 15, ty = tid >> 4;
    float blocksum = 0.f;

    for (int pp = slot; pp < npairs; pp += NSLOT) {
        int p = 0, rm = pp;
        while (rm >= nch - p) { rm -= nch - p; p++; }
        const int q = p + rm;

        for (int e = tid; e < CH * 32; e += 256) {
            int r = e >> 5, seg = e & 31;
            float4 wa = make_float4(0.f, 0.f, 0.f, 0.f), wb = wa;
            if (p * CH + r < n) wa = *(const float4*)(g_u + list[p * CH + r] * 128 + seg * 4);
            if (q * CH + r < n) wb = *(const float4*)(g_u + list[q * CH + r] * 128 + seg * 4);
            int d0 = seg * 4;
            uA[(d0 + 0) * PB_STRIDE + r] = wa.x; uA[(d0 + 1) * PB_STRIDE + r] = wa.y;
            uA[(d0 + 2) * PB_STRIDE + r] = wa.z; uA[(d0 + 3) * PB_STRIDE + r] = wa.w;
            uB[(d0 + 0) * PB_STRIDE + r] = wb.x; uB[(d0 + 1) * PB_STRIDE + r] = wb.y;
            uB[(d0 + 2) * PB_STRIDE + r] = wb.z; uB[(d0 + 3) * PB_STRIDE + r] = wb.w;
        }
        __syncthreads();

        float acc[4][4];
        #pragma unroll
        for (int a = 0; a < 4; a++)
            #pragma unroll
            for (int b = 0; b < 4; b++) acc[a][b] = 0.f;

        #pragma unroll 4
        for (int k = 0; k < 128; k++) {
            float ra[4], rb[4];
            *(float4*)ra = *(float4*)&uA[k * PB_STRIDE + tx * 4];
            *(float4*)rb = *(float4*)&uB[k * PB_STRIDE + ty * 4];
            #pragma unroll
            for (int a = 0; a < 4; a++)
                #pragma unroll
                for (int b = 0; b < 4; b++)
                    acc[a][b] = fmaf(ra[a], rb[b], acc[a][b]);
        }

        #pragma unroll
        for (int a = 0; a < 4; a++) {
            int X = p * CH + tx * 4 + a;
            #pragma unroll
            for (int b = 0; b < 4; b++) {
                int Y = q * CH + ty * 4 + b;
                if (X < n && Y < n && (p < q || X < Y)) {
                    float S = acc[a][b];
                    float e = __expf(S);
                    blocksum += 2.f * S - __logf(g_negsum[list[Y]] + e)
                                        - __logf(g_negsum[list[X]] + e);
                }
            }
        }
        __syncthreads();
    }

    float tot = blocksum;
    #pragma unroll
    for (int o = 16; o > 0; o >>= 1)
        tot += __shfl_xor_sync(0xffffffffu, tot, o);
    if ((tid & 31) == 0) red[tid >> 5] = tot;
    __syncthreads();
    if (tid == 0) {
        float s = 0.f;
        #pragma unroll
        for (int w = 0; w < 8; w++) s += red[w];
        atomicAdd(&g_loss, s);
    }
}

__global__ void fin_kernel(float* __restrict__ out) {
    out[0] = -g_loss / (float)NROWS;
}

// ----------------------------------------------------------------
extern "C" void kernel_launch(void* const* d_in, const int* in_sizes, int n_in,
                              void* d_out, int out_size) {
    const float* F  = (const float*)d_in[0];
    const int*   Li = (const int*)d_in[1];

    cudaFuncSetAttribute(passA_kernel, cudaFuncAttributeMaxDynamicSharedMemorySize, PASSA_SMEM);
    cudaFuncSetAttribute(passB_kernel, cudaFuncAttributeMaxDynamicSharedMemorySize, PASSB_SMEM);

    detect_kernel<<<1, 256>>>(Li);
    norm_kernel<<<NROWS, 128>>>(F, Li);
    build_kernel<<<NCLS, 256>>>();
    passA_kernel<<<2080, 256, PASSA_SMEM>>>();
    passB_kernel<<<NCLS * NSLOT, 256, PASSB_SMEM>>>();
    fin_kernel<<<1, 1>>>((float*)d_out);
}

// round 13
// speedup vs baseline: 1.8347x; 1.1347x over previous
#include <cuda_runtime.h>
#include <cuda_fp16.h>
#include <cstdint>

// SupConLoss: features [4096,2,128] f32, labels [4096] int(32|64) -> scalar f32
// N=8192. S[i,j]=dot(u'_i,u'_j), u' = normalized * (1/sqrt T).
// pass A: mma.sync fp16 hi/lo split, upper-tri 128x128 tiles, 3-slot panel staging
//         (HL->HH->LH term order) so smem fits 2 CTAs/SM.
// build: per-class ordered row lists. pass B: positive pairs, fp32 recompute.

#define NROWS 8192
#define BQ    4096
#define NCLS  100
#define RSQRT_T 3.77964473009227f   // 1/sqrt(0.07)

__device__ float  g_u [NROWS * 128];
__device__ __half g_uh[NROWS * 128];
__device__ __half g_ul[NROWS * 128];
__device__ int    g_lab[NROWS];
__device__ float  g_negsum[NROWS];
__device__ float  g_loss;
__device__ int    g_is64;

#define LCAP  640
__device__ int    g_list[NCLS * LCAP];
__device__ int    g_cnt[NCLS];

__device__ __forceinline__ uint32_t smem_u32(const void* p) {
    uint32_t a;
    asm("{ .reg .u64 t; cvta.to.shared.u64 t, %1; cvt.u32.u64 %0, t; }" : "=r"(a) : "l"(p));
    return a;
}

#define CP_ASYNC16(dst, src) \
    asm volatile("cp.async.ca.shared.global [%0], [%1], 16;" \
        :: "r"((uint32_t)(dst)), "l"(__cvta_generic_to_global((const void*)(src))) : "memory")
#define CP_ASYNC_COMMIT() asm volatile("cp.async.commit_group;" ::: "memory")
#define CP_ASYNC_WAIT_GROUP(n) asm volatile("cp.async.wait_group %0;" :: "n"(n) : "memory")

#define LDSM_X4(R, addr) \
    asm volatile("ldmatrix.sync.aligned.m8n8.x4.shared.b16 {%0,%1,%2,%3}, [%4];" \
        : "=r"((R)[0]), "=r"((R)[1]), "=r"((R)[2]), "=r"((R)[3]) : "r"(addr))

#define MMA16816(D, A, B0, B1) \
    asm volatile("mma.sync.aligned.m16n8k16.row.col.f32.f16.f16.f32 " \
        "{%0,%1,%2,%3}, {%4,%5,%6,%7}, {%8,%9}, {%0,%1,%2,%3};" \
        : "+f"((D)[0]), "+f"((D)[1]), "+f"((D)[2]), "+f"((D)[3]) \
        : "r"((A)[0]), "r"((A)[1]), "r"((A)[2]), "r"((A)[3]), "r"(B0), "r"(B1))

// ---------------------------------------------------------------- detect int64/int32
__global__ void detect_kernel(const int* __restrict__ Li) {
    __shared__ int nz;
    if (threadIdx.x == 0) nz = 0;
    __syncthreads();
    for (int i = threadIdx.x; i < 2048; i += blockDim.x)
        if (Li[2 * i + 1] != 0) nz = 1;
    __syncthreads();
    if (threadIdx.x == 0) g_is64 = (nz == 0);
}

// ---------------------------------------------------------------- normalize + split
__global__ void norm_kernel(const float* __restrict__ F, const int* __restrict__ Li) {
    int i = blockIdx.x, d = threadIdx.x;
    int b = i & (BQ - 1), v = i >> 12;
    float f = F[b * 256 + v * 128 + d];

    float ss = f * f;
    #pragma unroll
    for (int off = 16; off > 0; off >>= 1)
        ss += __shfl_xor_sync(0xffffffffu, ss, off);
    __shared__ float w[4];
    int lane = d & 31, warp = d >> 5;
    if (lane == 0) w[warp] = ss;
    __syncthreads();
    float s = rsqrtf(w[0] + w[1] + w[2] + w[3]) * RSQRT_T;

    float u = f * s;
    __half h = __float2half_rn(u);
    g_u [i * 128 + d] = u;
    g_uh[i * 128 + d] = h;
    g_ul[i * 128 + d] = __float2half_rn(u - __half2float(h));

    if (d == 0) {
        g_lab[i]    = g_is64 ? Li[2 * b] : Li[b];
        g_negsum[i] = 0.f;
        if (i == 0) g_loss = 0.f;
    }
}

// ---------------------------------------------------------------- build class lists
__global__ void build_kernel() {
    __shared__ int cnts[256];
    const int cls = blockIdx.x, tid = threadIdx.x;

    int base = tid * 32, cnt = 0;
    #pragma unroll
    for (int k = 0; k < 32; k++) cnt += (g_lab[base + k] == cls);
    cnts[tid] = cnt;
    __syncthreads();
    #pragma unroll
    for (int dd = 1; dd < 256; dd <<= 1) {
        int v = cnts[tid];
        int a = (tid >= dd) ? cnts[tid - dd] : 0;
        __syncthreads();
        cnts[tid] = v + a;
        __syncthreads();
    }
    if (tid == 255) g_cnt[cls] = (cnts[255] > LCAP) ? LCAP : cnts[255];
    int off = cnts[tid] - cnt;
    #pragma unroll
    for (int k = 0; k < 32; k++)
        if (g_lab[base + k] == cls && off < LCAP) g_list[cls * LCAP + off++] = base + k;
}

// ---------------------------------------------------------------- pass A
// 3 panel slots of 128 rows x 128 halves (272B stride), term order HL, HH, LH
#define PAN   34816u
#define O_S0  0u
#define O_S1  34816u
#define O_S2  69632u
#define O_LAB 104448u
#define O_RED 105472u
#define PASSA_SMEM 106496

__device__ __forceinline__ void load_panel(uint32_t sa, uint32_t slot, int tid,
                                           const __half* src, int rbase) {
    #pragma unroll
    for (int t = 0; t < 8; t++) {
        int f = tid + t * 256;
        int r = f >> 4, c = f & 15;
        CP_ASYNC16(sa + slot + r * 272 + c * 16,
                   (const char*)(src + (rbase + r) * 128) + c * 16);
    }
}

__device__ __forceinline__ void do_term(float d[2][8][4], uint32_t aBase, uint32_t bBase) {
    #pragma unroll
    for (int kk = 0; kk < 8; kk++) {
        uint32_t A[2][4], B[4][4];
        #pragma unroll
        for (int ma = 0; ma < 2; ma++)
            LDSM_X4(A[ma], aBase + kk * 32 + ma * 16 * 272);
        #pragma unroll
        for (int g = 0; g < 4; g++)
            LDSM_X4(B[g], bBase + kk * 32 + g * 16 * 272);
        #pragma unroll
        for (int ma = 0; ma < 2; ma++)
            #pragma unroll
            for (int nb = 0; nb < 8; nb++) {
                const int g = nb >> 1, h = nb & 1;
                MMA16816(d[ma][nb], A[ma], B[g][h], B[g][h + 2]);
            }
    }
}

__global__ __launch_bounds__(256, 2) void passA_kernel() {
    extern __shared__ char sm[];
    const uint32_t sa = smem_u32(sm);
    const int tid = threadIdx.x, wid = tid >> 5, lane = tid & 31;

    // upper-triangle tile index (64x64 tiles)
    int rem = blockIdx.x, ti = 0;
    while (rem >= 64 - ti) { rem -= 64 - ti; ti++; }
    const int tj = ti + rem;
    const int i0 = ti * 128, j0 = tj * 128;
    const bool diag = (ti == tj);

    int*   li_s  = (int*)(sm + O_LAB);
    int*   lj_s  = li_s + 128;
    float* s_row = (float*)(sm + O_RED);
    float* s_col = s_row + 128;

    ((float*)(sm + O_RED))[tid] = 0.f;
    if (tid < 128) { li_s[tid] = g_lab[i0 + tid]; lj_s[tid] = g_lab[j0 + tid]; }

    // warp addressing: 8 warps, 4x2 grid, 32x64 per warp
    const int wm = (wid >> 1) * 32;
    const int wn = (wid & 1) * 64;
    const int lrow = (lane & 7) + ((lane >> 3) & 1) * 8;
    const int lk   = (lane >> 4) * 8;
    const uint32_t aOffRow = (uint32_t)((wm + lrow) * 272 + lk * 2);
    const uint32_t bOffRow = (uint32_t)((wn + lrow) * 272 + lk * 2);

    float d[2][8][4];
    #pragma unroll
    for (int a = 0; a < 2; a++)
        #pragma unroll
        for (int b = 0; b < 8; b++)
            #pragma unroll
            for (int c = 0; c < 4; c++) d[a][b][c] = 0.f;

    if (diag) {
        // S0 = A_hi, S1 = A_lo; terms HL(S0,S1), HH(S0,S0), LH(S1,S0)
        load_panel(sa, O_S0, tid, g_uh, i0);
        load_panel(sa, O_S1, tid, g_ul, i0);
        CP_ASYNC_COMMIT();
        CP_ASYNC_WAIT_GROUP(0);
        __syncthreads();
        do_term(d, sa + O_S0 + aOffRow, sa + O_S1 + bOffRow);
        do_term(d, sa + O_S0 + aOffRow, sa + O_S0 + bOffRow);
        do_term(d, sa + O_S1 + aOffRow, sa + O_S0 + bOffRow);
    } else {
        // g0: S0 = A_hi, S1 = B_lo;  g1: S2 = B_hi;  (after HL)  g2: S1 = A_lo
        load_panel(sa, O_S0, tid, g_uh, i0);
        load_panel(sa, O_S1, tid, g_ul, j0);
        CP_ASYNC_COMMIT();                      // group 0
        load_panel(sa, O_S2, tid, g_uh, j0);
        CP_ASYNC_COMMIT();                      // group 1
        CP_ASYNC_WAIT_GROUP(1);                 // S0,S1 ready
        __syncthreads();
        do_term(d, sa + O_S0 + aOffRow, sa + O_S1 + bOffRow);   // HL: Ah x Bl
        __syncthreads();                        // all warps done reading S1
        load_panel(sa, O_S1, tid, g_ul, i0);
        CP_ASYNC_COMMIT();                      // group 2
        CP_ASYNC_WAIT_GROUP(1);                 // S2 (B_hi) ready
        __syncthreads();
        do_term(d, sa + O_S0 + aOffRow, sa + O_S2 + bOffRow);   // HH: Ah x Bh
        CP_ASYNC_WAIT_GROUP(0);                 // S1 (A_lo) ready
        __syncthreads();
        do_term(d, sa + O_S1 + aOffRow, sa + O_S2 + bOffRow);   // LH: Al x Bh
    }

    // ---- fused epilogue: masked exp, row/col sums ----
    const int grp = lane >> 2, q = lane & 3;
    float rs[2][2];
    rs[0][0] = rs[0][1] = rs[1][0] = rs[1][1] = 0.f;
    float cs[8][2];
    #pragma unroll
    for (int nb = 0; nb < 8; nb++) cs[nb][0] = cs[nb][1] = 0.f;

    #pragma unroll
    for (int ma = 0; ma < 2; ma++) {
        const int r0 = wm + ma * 16 + grp, r1 = r0 + 8;
        const int l0 = li_s[r0], l1 = li_s[r1];
        #pragma unroll
        for (int nb = 0; nb < 8; nb++) {
            const int c0 = wn + nb * 8 + q * 2;
            const int lc0 = lj_s[c0], lc1 = lj_s[c0 + 1];
            float v00 = (l0 != lc0) ? __expf(d[ma][nb][0]) : 0.f;
            float v01 = (l0 != lc1) ? __expf(d[ma][nb][1]) : 0.f;
            float v10 = (l1 != lc0) ? __expf(d[ma][nb][2]) : 0.f;
            float v11 = (l1 != lc1) ? __expf(d[ma][nb][3]) : 0.f;
            rs[ma][0] += v00 + v01;
            rs[ma][1] += v10 + v11;
            cs[nb][0] += v00 + v10;
            cs[nb][1] += v01 + v11;
        }
    }

    #pragma unroll
    for (int o = 1; o <= 2; o <<= 1) {
        #pragma unroll
        for (int ma = 0; ma < 2; ma++) {
            rs[ma][0] += __shfl_xor_sync(0xffffffffu, rs[ma][0], o);
            rs[ma][1] += __shfl_xor_sync(0xffffffffu, rs[ma][1], o);
        }
    }
    if (q == 0) {
        #pragma unroll
        for (int ma = 0; ma < 2; ma++) {
            atomicAdd(&s_row[wm + ma * 16 + grp],     rs[ma][0]);
            atomicAdd(&s_row[wm + ma * 16 + grp + 8], rs[ma][1]);
        }
    }

    #pragma unroll
    for (int o = 4; o <= 16; o <<= 1)
        #pragma unroll
        for (int nb = 0; nb < 8; nb++) {
            cs[nb][0] += __shfl_xor_sync(0xffffffffu, cs[nb][0], o);
            cs[nb][1] += __shfl_xor_sync(0xffffffffu, cs[nb][1], o);
        }
    if (grp == 0) {
        #pragma unroll
        for (int nb = 0; nb < 8; nb++) {
            atomicAdd(&s_col[wn + nb * 8 + q * 2],     cs[nb][0]);
            atomicAdd(&s_col[wn + nb * 8 + q * 2 + 1], cs[nb][1]);
        }
    }
    __syncthreads();

    if (tid < 128) {
        atomicAdd(&g_negsum[j0 + tid], s_col[tid]);
        if (!diag) atomicAdd(&g_negsum[i0 + tid], s_row[tid]);
    }
}

// ---------------------------------------------------------------- pass B: positive pairs
#define NSLOT 15
#define CH    64
#define PB_STRIDE 68
#define PASSB_SMEM (2 * 128 * PB_STRIDE * 4 + 64)

__global__ __launch_bounds__(256, 3) void passB_kernel() {
    extern __shared__ char smB[];
    float* uA  = (float*)smB;
    float* uB  = uA + 128 * PB_STRIDE;
    float* red = uB + 128 * PB_STRIDE;

    const int cls  = blockIdx.x / NSLOT;
    const int slot = blockIdx.x % NSLOT;
    const int tid  = threadIdx.x;

    const int n = g_cnt[cls];
    if (n < 2) return;
    const int nch = (n + CH - 1) / CH;
    const int npairs = nch * (nch + 1) / 2;
    if (slot >= npairs) return;

    const int* list = g_list + cls * LCAP;
    const int tx = tid & 15, ty = tid >> 4;
    float blocksum = 0.f;

    for (int pp = slot; pp < npairs; pp += NSLOT) {
        int p = 0, rm = pp;
        while (rm >= nch - p) { rm -= nch - p; p++; }
        const int q = p + rm;

        for (int e = tid; e < CH * 32; e += 256) {
            int r = e >> 5, seg = e & 31;
            float4 wa = make_float4(0.f, 0.f, 0.f, 0.f), wb = wa;
            if (p * CH + r < n) wa = *(const float4*)(g_u + list[p * CH + r] * 128 + seg * 4);
            if (q * CH + r < n) wb = *(const float4*)(g_u + list[q * CH + r] * 128 + seg * 4);
            int d0 = seg * 4;
            uA[(d0 + 0) * PB_STRIDE + r] = wa.x; uA[(d0 + 1) * PB_STRIDE + r] = wa.y;
            uA[(d0 + 2) * PB_STRIDE + r] = wa.z; uA[(d0 + 3) * PB_STRIDE + r] = wa.w;
            uB[(d0 + 0) * PB_STRIDE + r] = wb.x; uB[(d0 + 1) * PB_STRIDE + r] = wb.y;
            uB[(d0 + 2) * PB_STRIDE + r] = wb.z; uB[(d0 + 3) * PB_STRIDE + r] = wb.w;
        }
        __syncthreads();

        float acc[4][4];
        #pragma unroll
        for (int a = 0; a < 4; a++)
            #pragma unroll
            for (int b = 0; b < 4; b++) acc[a][b] = 0.f;

        #pragma unroll 4
        for (int k = 0; k < 128; k++) {
            float ra[4], rb[4];
            *(float4*)ra = *(float4*)&uA[k * PB_STRIDE + tx * 4];
            *(float4*)rb = *(float4*)&uB[k * PB_STRIDE + ty * 4];
            #pragma unroll
            for (int a = 0; a < 4; a++)
                #pragma unroll
                for (int b = 0; b < 4; b++)
                    acc[a][b] = fmaf(ra[a], rb[b], acc[a][b]);
        }

        #pragma unroll
        for (int a = 0; a < 4; a++) {
            int X = p * CH + tx * 4 + a;
            #pragma unroll
            for (int b = 0; b < 4; b++) {
                int Y = q * CH + ty * 4 + b;
                if (X < n && Y < n && (p < q || X < Y)) {
                    float S = acc[a][b];
                    float e = __expf(S);
                    blocksum += 2.f * S - __logf(g_negsum[list[Y]] + e)
                                        - __logf(g_negsum[list[X]] + e);
                }
            }
        }
        __syncthreads();
    }

    float tot = blocksum;
    #pragma unroll
    for (int o = 16; o > 0; o >>= 1)
        tot += __shfl_xor_sync(0xffffffffu, tot, o);
    if ((tid & 31) == 0) red[tid >> 5] = tot;
    __syncthreads();
    if (tid == 0) {
        float s = 0.f;
        #pragma unroll
        for (int w = 0; w < 8; w++) s += red[w];
        atomicAdd(&g_loss, s);
    }
}

__global__ void fin_kernel(float* __restrict__ out) {
    out[0] = -g_loss / (float)NROWS;
}

// ----------------------------------------------------------------
extern "C" void kernel_launch(void* const* d_in, const int* in_sizes, int n_in,
                              void* d_out, int out_size) {
    const float* F  = (const float*)d_in[0];
    const int*   Li = (const int*)d_in[1];

    cudaFuncSetAttribute(passA_kernel, cudaFuncAttributeMaxDynamicSharedMemorySize, PASSA_SMEM);
    cudaFuncSetAttribute(passB_kernel, cudaFuncAttributeMaxDynamicSharedMemorySize, PASSB_SMEM);

    detect_kernel<<<1, 256>>>(Li);
    norm_kernel<<<NROWS, 128>>>(F, Li);
    build_kernel<<<NCLS, 256>>>();
    passA_kernel<<<2080, 256, PASSA_SMEM>>>();
    passB_kernel<<<NCLS * NSLOT, 256, PASSB_SMEM>>>();
    fin_kernel<<<1, 1>>>((float*)d_out);
}

// round 15
// speedup vs baseline: 2.4221x; 1.3201x over previous
#include <cuda_runtime.h>
#include <cuda_fp16.h>
#include <cstdint>

// SupConLoss: features [4096,2,128] f32, labels [4096] int(32|64) -> scalar f32
// N=8192. S[i,j]=dot(u'_i,u'_j), u' = normalized * (1/sqrt T).
// pass A: single-term fp16 mma.sync (ns needs only ~1e-4 accuracy; positives are
//         recomputed exactly in fp32 in pass B). Upper-tri 128x128 tiles.
// build: per-class ordered row lists. pass B: positive pairs, fp32 recompute.

#define NROWS 8192
#define BQ    4096
#define NCLS  100
#define RSQRT_T 3.77964473009227f   // 1/sqrt(0.07)

__device__ float  g_u [NROWS * 128];
__device__ __half g_uh[NROWS * 128];
__device__ int    g_lab[NROWS];
__device__ float  g_negsum[NROWS];
__device__ float  g_loss;
__device__ int    g_is64;

#define LCAP  640
__device__ int    g_list[NCLS * LCAP];
__device__ int    g_cnt[NCLS];

__device__ __forceinline__ uint32_t smem_u32(const void* p) {
    uint32_t a;
    asm("{ .reg .u64 t; cvta.to.shared.u64 t, %1; cvt.u32.u64 %0, t; }" : "=r"(a) : "l"(p));
    return a;
}

#define CP_ASYNC16(dst, src) \
    asm volatile("cp.async.ca.shared.global [%0], [%1], 16;" \
        :: "r"((uint32_t)(dst)), "l"(__cvta_generic_to_global((const void*)(src))) : "memory")
#define CP_ASYNC_COMMIT() asm volatile("cp.async.commit_group;" ::: "memory")
#define CP_ASYNC_WAIT_GROUP(n) asm volatile("cp.async.wait_group %0;" :: "n"(n) : "memory")

#define LDSM_X4(R, addr) \
    asm volatile("ldmatrix.sync.aligned.m8n8.x4.shared.b16 {%0,%1,%2,%3}, [%4];" \
        : "=r"((R)[0]), "=r"((R)[1]), "=r"((R)[2]), "=r"((R)[3]) : "r"(addr))

#define MMA16816(D, A, B0, B1) \
    asm volatile("mma.sync.aligned.m16n8k16.row.col.f32.f16.f16.f32 " \
        "{%0,%1,%2,%3}, {%4,%5,%6,%7}, {%8,%9}, {%0,%1,%2,%3};" \
        : "+f"((D)[0]), "+f"((D)[1]), "+f"((D)[2]), "+f"((D)[3]) \
        : "r"((A)[0]), "r"((A)[1]), "r"((A)[2]), "r"((A)[3]), "r"(B0), "r"(B1))

// ---------------------------------------------------------------- detect int64/int32
__global__ void detect_kernel(const int* __restrict__ Li) {
    __shared__ int nz;
    if (threadIdx.x == 0) nz = 0;
    __syncthreads();
    for (int i = threadIdx.x; i < 2048; i += blockDim.x)
        if (Li[2 * i + 1] != 0) nz = 1;
    __syncthreads();
    if (threadIdx.x == 0) g_is64 = (nz == 0);
}

// ---------------------------------------------------------------- normalize
__global__ void norm_kernel(const float* __restrict__ F, const int* __restrict__ Li) {
    int i = blockIdx.x, d = threadIdx.x;
    int b = i & (BQ - 1), v = i >> 12;
    float f = F[b * 256 + v * 128 + d];

    float ss = f * f;
    #pragma unroll
    for (int off = 16; off > 0; off >>= 1)
        ss += __shfl_xor_sync(0xffffffffu, ss, off);
    __shared__ float w[4];
    int lane = d & 31, warp = d >> 5;
    if (lane == 0) w[warp] = ss;
    __syncthreads();
    float s = rsqrtf(w[0] + w[1] + w[2] + w[3]) * RSQRT_T;

    float u = f * s;
    g_u [i * 128 + d] = u;
    g_uh[i * 128 + d] = __float2half_rn(u);

    if (d == 0) {
        g_lab[i]    = g_is64 ? Li[2 * b] : Li[b];
        g_negsum[i] = 0.f;
        if (i == 0) g_loss = 0.f;
    }
}

// ---------------------------------------------------------------- build class lists
__global__ void build_kernel() {
    __shared__ int cnts[256];
    const int cls = blockIdx.x, tid = threadIdx.x;

    int base = tid * 32, cnt = 0;
    #pragma unroll
    for (int k = 0; k < 32; k++) cnt += (g_lab[base + k] == cls);
    cnts[tid] = cnt;
    __syncthreads();
    #pragma unroll
    for (int dd = 1; dd < 256; dd <<= 1) {
        int v = cnts[tid];
        int a = (tid >= dd) ? cnts[tid - dd] : 0;
        __syncthreads();
        cnts[tid] = v + a;
        __syncthreads();
    }
    if (tid == 255) g_cnt[cls] = (cnts[255] > LCAP) ? LCAP : cnts[255];
    int off = cnts[tid] - cnt;
    #pragma unroll
    for (int k = 0; k < 32; k++)
        if (g_lab[base + k] == cls && off < LCAP) g_list[cls * LCAP + off++] = base + k;
}

// ---------------------------------------------------------------- pass A
// 2 panel slots of 128 rows x 128 halves (272B stride)
#define PAN   34816u
#define O_S0  0u
#define O_S1  34816u
#define O_LAB 69632u
#define O_RED 70656u
#define PASSA_SMEM 71680

__device__ __forceinline__ void load_panel(uint32_t sa, uint32_t slot, int tid,
                                           const __half* src, int rbase) {
    #pragma unroll
    for (int t = 0; t < 8; t++) {
        int f = tid + t * 256;
        int r = f >> 4, c = f & 15;
        CP_ASYNC16(sa + slot + r * 272 + c * 16,
                   (const char*)(src + (rbase + r) * 128) + c * 16);
    }
}

__global__ __launch_bounds__(256, 2) void passA_kernel() {
    extern __shared__ char sm[];
    const uint32_t sa = smem_u32(sm);
    const int tid = threadIdx.x, wid = tid >> 5, lane = tid & 31;

    // upper-triangle tile index (64x64 tiles)
    int rem = blockIdx.x, ti = 0;
    while (rem >= 64 - ti) { rem -= 64 - ti; ti++; }
    const int tj = ti + rem;
    const int i0 = ti * 128, j0 = tj * 128;
    const bool diag = (ti == tj);

    int*   li_s  = (int*)(sm + O_LAB);
    int*   lj_s  = li_s + 128;
    float* s_row = (float*)(sm + O_RED);
    float* s_col = s_row + 128;

    ((float*)(sm + O_RED))[tid] = 0.f;
    if (tid < 128) { li_s[tid] = g_lab[i0 + tid]; lj_s[tid] = g_lab[j0 + tid]; }

    // panel fill (B aliases A on the diagonal)
    load_panel(sa, O_S0, tid, g_uh, i0);
    if (!diag) load_panel(sa, O_S1, tid, g_uh, j0);
    CP_ASYNC_COMMIT();
    CP_ASYNC_WAIT_GROUP(0);
    __syncthreads();

    // 8 warps: 4x2 grid, each warp 32x64 output
    const int wm = (wid >> 1) * 32;
    const int wn = (wid & 1) * 64;
    const int lrow = (lane & 7) + ((lane >> 3) & 1) * 8;
    const int lk   = (lane >> 4) * 8;
    const uint32_t aBase = sa + O_S0 + (uint32_t)((wm + lrow) * 272 + lk * 2);
    const uint32_t bBase = sa + (diag ? O_S0 : O_S1) + (uint32_t)((wn + lrow) * 272 + lk * 2);

    float d[2][8][4];
    #pragma unroll
    for (int a = 0; a < 2; a++)
        #pragma unroll
        for (int b = 0; b < 8; b++)
            #pragma unroll
            for (int c = 0; c < 4; c++) d[a][b][c] = 0.f;

    #pragma unroll
    for (int kk = 0; kk < 8; kk++) {
        uint32_t A[2][4], B[4][4];
        #pragma unroll
        for (int ma = 0; ma < 2; ma++)
            LDSM_X4(A[ma], aBase + kk * 32 + ma * 16 * 272);
        #pragma unroll
        for (int g = 0; g < 4; g++)
            LDSM_X4(B[g], bBase + kk * 32 + g * 16 * 272);
        #pragma unroll
        for (int ma = 0; ma < 2; ma++)
            #pragma unroll
            for (int nb = 0; nb < 8; nb++) {
                const int g = nb >> 1, h = nb & 1;
                MMA16816(d[ma][nb], A[ma], B[g][h], B[g][h + 2]);
            }
    }

    // ---- fused epilogue: masked exp, row/col sums ----
    const int grp = lane >> 2, q = lane & 3;
    float rs[2][2];
    rs[0][0] = rs[0][1] = rs[1][0] = rs[1][1] = 0.f;
    float cs[8][2];
    #pragma unroll
    for (int nb = 0; nb < 8; nb++) cs[nb][0] = cs[nb][1] = 0.f;

    #pragma unroll
    for (int ma = 0; ma < 2; ma++) {
        const int r0 = wm + ma * 16 + grp, r1 = r0 + 8;
        const int l0 = li_s[r0], l1 = li_s[r1];
        #pragma unroll
        for (int nb = 0; nb < 8; nb++) {
            const int c0 = wn + nb * 8 + q * 2;
            const int lc0 = lj_s[c0], lc1 = lj_s[c0 + 1];
            float v00 = (l0 != lc0) ? __expf(d[ma][nb][0]) : 0.f;
            float v01 = (l0 != lc1) ? __expf(d[ma][nb][1]) : 0.f;
            float v10 = (l1 != lc0) ? __expf(d[ma][nb][2]) : 0.f;
            float v11 = (l1 != lc1) ? __expf(d[ma][nb][3]) : 0.f;
            rs[ma][0] += v00 + v01;
            rs[ma][1] += v10 + v11;
            cs[nb][0] += v00 + v10;
            cs[nb][1] += v01 + v11;
        }
    }

    #pragma unroll
    for (int o = 1; o <= 2; o <<= 1) {
        #pragma unroll
        for (int ma = 0; ma < 2; ma++) {
            rs[ma][0] += __shfl_xor_sync(0xffffffffu, rs[ma][0], o);
            rs[ma][1] += __shfl_xor_sync(0xffffffffu, rs[ma][1], o);
        }
    }
    if (q == 0) {
        #pragma unroll
        for (int ma = 0; ma < 2; ma++) {
            atomicAdd(&s_row[wm + ma * 16 + grp],     rs[ma][0]);
            atomicAdd(&s_row[wm + ma * 16 + grp + 8], rs[ma][1]);
        }
    }

    #pragma unroll
    for (int o = 4; o <= 16; o <<= 1)
        #pragma unroll
        for (int nb = 0; nb < 8; nb++) {
            cs[nb][0] += __shfl_xor_sync(0xffffffffu, cs[nb][0], o);
            cs[nb][1] += __shfl_xor_sync(0xffffffffu, cs[nb][1], o);
        }
    if (grp == 0) {
        #pragma unroll
        for (int nb = 0; nb < 8; nb++) {
            atomicAdd(&s_col[wn + nb * 8 + q * 2],     cs[nb][0]);
            atomicAdd(&s_col[wn + nb * 8 + q * 2 + 1], cs[nb][1]);
        }
    }
    __syncthreads();

    if (tid < 128) {
        atomicAdd(&g_negsum[j0 + tid], s_col[tid]);
        if (!diag) atomicAdd(&g_negsum[i0 + tid], s_row[tid]);
    }
}

// ---------------------------------------------------------------- pass B: positive pairs
#define NSLOT 15
#define CH    64
#define PB_STRIDE 68
#define PASSB_SMEM (2 * 128 * PB_STRIDE * 4 + 64)

__global__ __launch_bounds__(256, 3) void passB_kernel() {
    extern __shared__ char smB[];
    float* uA  = (float*)smB;
    float* uB  = uA + 128 * PB_STRIDE;
    float* red = uB + 128 * PB_STRIDE;

    const int cls  = blockIdx.x / NSLOT;
    const int slot = blockIdx.x % NSLOT;
    const int tid  = threadIdx.x;

    const int n = g_cnt[cls];
    if (n < 2) return;
    const int nch = (n + CH - 1) / CH;
    const int npairs = nch * (nch + 1) / 2;
    if (slot >= npairs) return;

    const int* list = g_list + cls * LCAP;
    const int tx = tid & 15, ty = tid >> 4;
    float blocksum = 0.f;

    for (int pp = slot; pp < npairs; pp += NSLOT) {
        int p = 0, rm = pp;
        while (rm >= nch - p) { rm -= nch - p; p++; }
        const int q = p + rm;

        for (int e = tid; e < CH * 32; e += 256) {
            int r = e >> 5, seg = e & 31;
            float4 wa = make_float4(0.f, 0.f, 0.f, 0.f), wb = wa;
            if (p * CH + r < n) wa = *(const float4*)(g_u + list[p * CH + r] * 128 + seg * 4);
            if (q * CH + r < n) wb = *(const float4*)(g_u + list[q * CH + r] * 128 + seg * 4);
            int d0 = seg * 4;
            uA[(d0 + 0) * PB_STRIDE + r] = wa.x; uA[(d0 + 1) * PB_STRIDE + r] = wa.y;
            uA[(d0 + 2) * PB_STRIDE + r] = wa.z; uA[(d0 + 3) * PB_STRIDE + r] = wa.w;
            uB[(d0 + 0) * PB_STRIDE + r] = wb.x; uB[(d0 + 1) * PB_STRIDE + r] = wb.y;
            uB[(d0 + 2) * PB_STRIDE + r] = wb.z; uB[(d0 + 3) * PB_STRIDE + r] = wb.w;
        }
        __syncthreads();

        float acc[4][4];
        #pragma unroll
        for (int a = 0; a < 4; a++)
            #pragma unroll
            for (int b = 0; b < 4; b++) acc[a][b] = 0.f;

        #pragma unroll 4
        for (int k = 0; k < 128; k++) {
            float ra[4], rb[4];
            *(float4*)ra = *(float4*)&uA[k * PB_STRIDE + tx * 4];
            *(float4*)rb = *(float4*)&uB[k * PB_STRIDE + ty * 4];
            #pragma unroll
            for (int a = 0; a < 4; a++)
                #pragma unroll
                for (int b = 0; b < 4; b++)
                    acc[a][b] = fmaf(ra[a], rb[b], acc[a][b]);
        }

        #pragma unroll
        for (int a = 0; a < 4; a++) {
            int X = p * CH + tx * 4 + a;
            #pragma unroll
            for (int b = 0; b < 4; b++) {
                int Y = q * CH + ty * 4 + b;
                if (X < n && Y < n && (p < q || X < Y)) {
                    float S = acc[a][b];
                    float e = __expf(S);
                    blocksum += 2.f * S - __logf(g_negsum[list[Y]] + e)
                                        - __logf(g_negsum[list[X]] + e);
                }
            }
        }
        __syncthreads();
    }

    float tot = blocksum;
    #pragma unroll
    for (int o = 16; o > 0; o >>= 1)
        tot += __shfl_xor_sync(0xffffffffu, tot, o);
    if ((tid & 31) == 0) red[tid >> 5] = tot;
    __syncthreads();
    if (tid == 0) {
        float s = 0.f;
        #pragma unroll
        for (int w = 0; w < 8; w++) s += red[w];
        atomicAdd(&g_loss, s);
    }
}

__global__ void fin_kernel(float* __restrict__ out) {
    out[0] = -g_loss / (float)NROWS;
}

// ----------------------------------------------------------------
extern "C" void kernel_launch(void* const* d_in, const int* in_sizes, int n_in,
                              void* d_out, int out_size) {
    const float* F  = (const float*)d_in[0];
    const int*   Li = (const int*)d_in[1];

    cudaFuncSetAttribute(passA_kernel, cudaFuncAttributeMaxDynamicSharedMemorySize, PASSA_SMEM);
    cudaFuncSetAttribute(passB_kernel, cudaFuncAttributeMaxDynamicSharedMemorySize, PASSB_SMEM);

    detect_kernel<<<1, 256>>>(Li);
    norm_kernel<<<NROWS, 128>>>(F, Li);
    build_kernel<<<NCLS, 256>>>();
    passA_kernel<<<2080, 256, PASSA_SMEM>>>();
    passB_kernel<<<NCLS * NSLOT, 256, PASSB_SMEM>>>();
    fin_kernel<<<1, 1>>>((float*)d_out);
}

// round 16
// speedup vs baseline: 2.4330x; 1.0045x over previous
#include <cuda_runtime.h>
#include <cuda_fp16.h>
#include <cstdint>

// SupConLoss: features [4096,2,128] f32, labels [4096] int(32|64) -> scalar f32
// N=8192. S[i,j]=dot(u'_i,u'_j), u' = normalized * (1/sqrt T).
// norm: warp-per-row normalize + fp16 cast.
// build: per-class ordered row lists (computes int64/int32 layout itself).
// pass A: single-term fp16 mma.sync, upper-tri 128x128 tiles, ns via symmetry.
// pass B: positive pairs, fp32 recompute; self-finalizing (completion ticket).

#define NROWS 8192
#define BQ    4096
#define NCLS  100
#define RSQRT_T 3.77964473009227f   // 1/sqrt(0.07)

__device__ float  g_u [NROWS * 128];
__device__ __half g_uh[NROWS * 128];
__device__ int    g_lab[NROWS];
__device__ float  g_negsum[NROWS];
__device__ float  g_loss;
__device__ int    g_done;

#define LCAP  640
__device__ int    g_list[NCLS * LCAP];
__device__ int    g_cnt[NCLS];

__device__ __forceinline__ uint32_t smem_u32(const void* p) {
    uint32_t a;
    asm("{ .reg .u64 t; cvta.to.shared.u64 t, %1; cvt.u32.u64 %0, t; }" : "=r"(a) : "l"(p));
    return a;
}

#define CP_ASYNC16(dst, src) \
    asm volatile("cp.async.ca.shared.global [%0], [%1], 16;" \
        :: "r"((uint32_t)(dst)), "l"(__cvta_generic_to_global((const void*)(src))) : "memory")
#define CP_ASYNC_COMMIT() asm volatile("cp.async.commit_group;" ::: "memory")
#define CP_ASYNC_WAIT_GROUP(n) asm volatile("cp.async.wait_group %0;" :: "n"(n) : "memory")

#define LDSM_X4(R, addr) \
    asm volatile("ldmatrix.sync.aligned.m8n8.x4.shared.b16 {%0,%1,%2,%3}, [%4];" \
        : "=r"((R)[0]), "=r"((R)[1]), "=r"((R)[2]), "=r"((R)[3]) : "r"(addr))

#define MMA16816(D, A, B0, B1) \
    asm volatile("mma.sync.aligned.m16n8k16.row.col.f32.f16.f16.f32 " \
        "{%0,%1,%2,%3}, {%4,%5,%6,%7}, {%8,%9}, {%0,%1,%2,%3};" \
        : "+f"((D)[0]), "+f"((D)[1]), "+f"((D)[2]), "+f"((D)[3]) \
        : "r"((A)[0]), "r"((A)[1]), "r"((A)[2]), "r"((A)[3]), "r"(B0), "r"(B1))

// ---------------------------------------------------------------- normalize (warp/row)
__global__ __launch_bounds__(256) void norm_kernel(const float* __restrict__ F) {
    const int w    = (blockIdx.x * 256 + threadIdx.x) >> 5;   // global warp = row
    const int lane = threadIdx.x & 31;
    const int b = w & (BQ - 1), v = w >> 12;

    float4 f = *(const float4*)(F + b * 256 + v * 128 + lane * 4);
    float ss = f.x * f.x + f.y * f.y + f.z * f.z + f.w * f.w;
    #pragma unroll
    for (int o = 16; o > 0; o >>= 1)
        ss += __shfl_xor_sync(0xffffffffu, ss, o);
    const float s = rsqrtf(ss) * RSQRT_T;

    float4 u = make_float4(f.x * s, f.y * s, f.z * s, f.w * s);
    *(float4*)(g_u + w * 128 + lane * 4) = u;
    __half2 h01 = __floats2half2_rn(u.x, u.y);
    __half2 h23 = __floats2half2_rn(u.z, u.w);
    uint2 hp;
    hp.x = *(uint32_t*)&h01;
    hp.y = *(uint32_t*)&h23;
    *(uint2*)(g_uh + w * 128 + lane * 4) = hp;

    if (lane == 0) {
        g_negsum[w] = 0.f;
        if (w == 0) { g_loss = 0.f; g_done = 0; }
    }
}

// ---------------------------------------------------------------- build class lists
// Also detects int64-vs-int32 label layout locally and (block 0) publishes g_lab.
__global__ void build_kernel(const int* __restrict__ Li) {
    __shared__ int cnts[256];
    __shared__ int s_nz;
    const int cls = blockIdx.x, tid = threadIdx.x;

    if (tid == 0) s_nz = 0;
    __syncthreads();
    for (int i = tid; i < 2048; i += 256)
        if (Li[2 * i + 1] != 0) s_nz = 1;
    __syncthreads();
    const bool is64 = (s_nz == 0);

    // label of row k (rows 0..8191, b = k & 4095)
    #define LAB(k) (is64 ? Li[2 * ((k) & (BQ - 1))] : Li[(k) & (BQ - 1)])

    if (cls == 0)
        for (int i = tid; i < NROWS; i += 256) g_lab[i] = LAB(i);

    const int base = tid * 32;
    int cnt = 0;
    #pragma unroll
    for (int k = 0; k < 32; k++) cnt += (LAB(base + k) == cls);
    cnts[tid] = cnt;
    __syncthreads();
    #pragma unroll
    for (int dd = 1; dd < 256; dd <<= 1) {
        int v = cnts[tid];
        int a = (tid >= dd) ? cnts[tid - dd] : 0;
        __syncthreads();
        cnts[tid] = v + a;
        __syncthreads();
    }
    if (tid == 255) g_cnt[cls] = (cnts[255] > LCAP) ? LCAP : cnts[255];
    int off = cnts[tid] - cnt;
    #pragma unroll
    for (int k = 0; k < 32; k++)
        if (LAB(base + k) == cls && off < LCAP) g_list[cls * LCAP + off++] = base + k;
    #undef LAB
}

// ---------------------------------------------------------------- pass A
// 2 panel slots of 128 rows x 128 halves (272B stride)
#define PAN   34816u
#define O_S0  0u
#define O_S1  34816u
#define O_LAB 69632u
#define O_RED 70656u
#define PASSA_SMEM 71680

__device__ __forceinline__ void load_panel(uint32_t sa, uint32_t slot, int tid,
                                           const __half* src, int rbase) {
    #pragma unroll
    for (int t = 0; t < 8; t++) {
        int f = tid + t * 256;
        int r = f >> 4, c = f & 15;
        CP_ASYNC16(sa + slot + r * 272 + c * 16,
                   (const char*)(src + (rbase + r) * 128) + c * 16);
    }
}

__global__ __launch_bounds__(256, 2) void passA_kernel() {
    extern __shared__ char sm[];
    const uint32_t sa = smem_u32(sm);
    const int tid = threadIdx.x, wid = tid >> 5, lane = tid & 31;

    // upper-triangle tile index (64x64 tiles)
    int rem = blockIdx.x, ti = 0;
    while (rem >= 64 - ti) { rem -= 64 - ti; ti++; }
    const int tj = ti + rem;
    const int i0 = ti * 128, j0 = tj * 128;
    const bool diag = (ti == tj);

    int*   li_s  = (int*)(sm + O_LAB);
    int*   lj_s  = li_s + 128;
    float* s_row = (float*)(sm + O_RED);
    float* s_col = s_row + 128;

    ((float*)(sm + O_RED))[tid] = 0.f;
    if (tid < 128) { li_s[tid] = g_lab[i0 + tid]; lj_s[tid] = g_lab[j0 + tid]; }

    // panel fill (B aliases A on the diagonal)
    load_panel(sa, O_S0, tid, g_uh, i0);
    if (!diag) load_panel(sa, O_S1, tid, g_uh, j0);
    CP_ASYNC_COMMIT();
    CP_ASYNC_WAIT_GROUP(0);
    __syncthreads();

    // 8 warps: 4x2 grid, each warp 32x64 output
    const int wm = (wid >> 1) * 32;
    const int wn = (wid & 1) * 64;
    const int lrow = (lane & 7) + ((lane >> 3) & 1) * 8;
    const int lk   = (lane >> 4) * 8;
    const uint32_t aBase = sa + O_S0 + (uint32_t)((wm + lrow) * 272 + lk * 2);
    const uint32_t bBase = sa + (diag ? O_S0 : O_S1) + (uint32_t)((wn + lrow) * 272 + lk * 2);

    float d[2][8][4];
    #pragma unroll
    for (int a = 0; a < 2; a++)
        #pragma unroll
        for (int b = 0; b < 8; b++)
            #pragma unroll
            for (int c = 0; c < 4; c++) d[a][b][c] = 0.f;

    #pragma unroll
    for (int kk = 0; kk < 8; kk++) {
        uint32_t A[2][4], B[4][4];
        #pragma unroll
        for (int ma = 0; ma < 2; ma++)
            LDSM_X4(A[ma], aBase + kk * 32 + ma * 16 * 272);
        #pragma unroll
        for (int g = 0; g < 4; g++)
            LDSM_X4(B[g], bBase + kk * 32 + g * 16 * 272);
        #pragma unroll
        for (int ma = 0; ma < 2; ma++)
            #pragma unroll
            for (int nb = 0; nb < 8; nb++) {
                const int g = nb >> 1, h = nb & 1;
                MMA16816(d[ma][nb], A[ma], B[g][h], B[g][h + 2]);
            }
    }

    // ---- fused epilogue: masked exp, row/col sums ----
    const int grp = lane >> 2, q = lane & 3;
    float rs[2][2];
    rs[0][0] = rs[0][1] = rs[1][0] = rs[1][1] = 0.f;
    float cs[8][2];
    #pragma unroll
    for (int nb = 0; nb < 8; nb++) cs[nb][0] = cs[nb][1] = 0.f;

    #pragma unroll
    for (int ma = 0; ma < 2; ma++) {
        const int r0 = wm + ma * 16 + grp, r1 = r0 + 8;
        const int l0 = li_s[r0], l1 = li_s[r1];
        #pragma unroll
        for (int nb = 0; nb < 8; nb++) {
            const int c0 = wn + nb * 8 + q * 2;
            const int lc0 = lj_s[c0], lc1 = lj_s[c0 + 1];
            float v00 = (l0 != lc0) ? __expf(d[ma][nb][0]) : 0.f;
            float v01 = (l0 != lc1) ? __expf(d[ma][nb][1]) : 0.f;
            float v10 = (l1 != lc0) ? __expf(d[ma][nb][2]) : 0.f;
            float v11 = (l1 != lc1) ? __expf(d[ma][nb][3]) : 0.f;
            rs[ma][0] += v00 + v01;
            rs[ma][1] += v10 + v11;
            cs[nb][0] += v00 + v10;
            cs[nb][1] += v01 + v11;
        }
    }

    #pragma unroll
    for (int o = 1; o <= 2; o <<= 1) {
        #pragma unroll
        for (int ma = 0; ma < 2; ma++) {
            rs[ma][0] += __shfl_xor_sync(0xffffffffu, rs[ma][0], o);
            rs[ma][1] += __shfl_xor_sync(0xffffffffu, rs[ma][1], o);
        }
    }
    if (q == 0) {
        #pragma unroll
        for (int ma = 0; ma < 2; ma++) {
            atomicAdd(&s_row[wm + ma * 16 + grp],     rs[ma][0]);
            atomicAdd(&s_row[wm + ma * 16 + grp + 8], rs[ma][1]);
        }
    }

    #pragma unroll
    for (int o = 4; o <= 16; o <<= 1)
        #pragma unroll
        for (int nb = 0; nb < 8; nb++) {
            cs[nb][0] += __shfl_xor_sync(0xffffffffu, cs[nb][0], o);
            cs[nb][1] += __shfl_xor_sync(0xffffffffu, cs[nb][1], o);
        }
    if (grp == 0) {
        #pragma unroll
        for (int nb = 0; nb < 8; nb++) {
            atomicAdd(&s_col[wn + nb * 8 + q * 2],     cs[nb][0]);
            atomicAdd(&s_col[wn + nb * 8 + q * 2 + 1], cs[nb][1]);
        }
    }
    __syncthreads();

    if (tid < 128) {
        atomicAdd(&g_negsum[j0 + tid], s_col[tid]);
        if (!diag) atomicAdd(&g_negsum[i0 + tid], s_row[tid]);
    }
}

// ---------------------------------------------------------------- pass B (+ finalize)
#define NSLOT 15
#define CH    64
#define PB_STRIDE 68
#define PASSB_SMEM (2 * 128 * PB_STRIDE * 4 + 64)

__global__ __launch_bounds__(256, 3) void passB_kernel(float* __restrict__ out) {
    extern __shared__ char smB[];
    float* uA  = (float*)smB;
    float* uB  = uA + 128 * PB_STRIDE;
    float* red = uB + 128 * PB_STRIDE;

    const int cls  = blockIdx.x / NSLOT;
    const int slot = blockIdx.x % NSLOT;
    const int tid  = threadIdx.x;

    const int n = g_cnt[cls];
    const int nch = (n + CH - 1) / CH;
    const int npairs = nch * (nch + 1) / 2;
    const bool active = (n >= 2) && (slot < npairs);

    if (active) {
        const int* list = g_list + cls * LCAP;
        const int tx = tid & 15, ty = tid >> 4;
        float blocksum = 0.f;

        for (int pp = slot; pp < npairs; pp += NSLOT) {
            int p = 0, rm = pp;
            while (rm >= nch - p) { rm -= nch - p; p++; }
            const int q = p + rm;

            for (int e = tid; e < CH * 32; e += 256) {
                int r = e >> 5, seg = e & 31;
                float4 wa = make_float4(0.f, 0.f, 0.f, 0.f), wb = wa;
                if (p * CH + r < n) wa = *(const float4*)(g_u + list[p * CH + r] * 128 + seg * 4);
                if (q * CH + r < n) wb = *(const float4*)(g_u + list[q * CH + r] * 128 + seg * 4);
                int d0 = seg * 4;
                uA[(d0 + 0) * PB_STRIDE + r] = wa.x; uA[(d0 + 1) * PB_STRIDE + r] = wa.y;
                uA[(d0 + 2) * PB_STRIDE + r] = wa.z; uA[(d0 + 3) * PB_STRIDE + r] = wa.w;
                uB[(d0 + 0) * PB_STRIDE + r] = wb.x; uB[(d0 + 1) * PB_STRIDE + r] = wb.y;
                uB[(d0 + 2) * PB_STRIDE + r] = wb.z; uB[(d0 + 3) * PB_STRIDE + r] = wb.w;
            }
            __syncthreads();

            float acc[4][4];
            #pragma unroll
            for (int a = 0; a < 4; a++)
                #pragma unroll
                for (int b = 0; b < 4; b++) acc[a][b] = 0.f;

            #pragma unroll 4
            for (int k = 0; k < 128; k++) {
                float ra[4], rb[4];
                *(float4*)ra = *(float4*)&uA[k * PB_STRIDE + tx * 4];
                *(float4*)rb = *(float4*)&uB[k * PB_STRIDE + ty * 4];
                #pragma unroll
                for (int a = 0; a < 4; a++)
                    #pragma unroll
                    for (int b = 0; b < 4; b++)
                        acc[a][b] = fmaf(ra[a], rb[b], acc[a][b]);
            }

            #pragma unroll
            for (int a = 0; a < 4; a++) {
                int X = p * CH + tx * 4 + a;
                #pragma unroll
                for (int b = 0; b < 4; b++) {
                    int Y = q * CH + ty * 4 + b;
                    if (X < n && Y < n && (p < q || X < Y)) {
                        float S = acc[a][b];
                        float e = __expf(S);
                        blocksum += 2.f * S - __logf(g_negsum[list[Y]] + e)
                                            - __logf(g_negsum[list[X]] + e);
                    }
                }
            }
            __syncthreads();
        }

        float tot = blocksum;
        #pragma unroll
        for (int o = 16; o > 0; o >>= 1)
            tot += __shfl_xor_sync(0xffffffffu, tot, o);
        if ((tid & 31) == 0) red[tid >> 5] = tot;
        __syncthreads();
        if (tid == 0) {
            float s = 0.f;
            #pragma unroll
            for (int w = 0; w < 8; w++) s += red[w];
            atomicAdd(&g_loss, s);
        }
    }

    // completion ticket: last block finalizes the output
    if (tid == 0) {
        __threadfence();
        int old = atomicAdd(&g_done, 1);
        if (old == (int)gridDim.x - 1) {
            __threadfence();
            out[0] = -g_loss / (float)NROWS;
        }
    }
}

// ----------------------------------------------------------------
extern "C" void kernel_launch(void* const* d_in, const int* in_sizes, int n_in,
                              void* d_out, int out_size) {
    const float* F  = (const float*)d_in[0];
    const int*   Li = (const int*)d_in[1];

    cudaFuncSetAttribute(passA_kernel, cudaFuncAttributeMaxDynamicSharedMemorySize, PASSA_SMEM);
    cudaFuncSetAttribute(passB_kernel, cudaFuncAttributeMaxDynamicSharedMemorySize, PASSB_SMEM);

    norm_kernel<<<NROWS / 8, 256>>>(F);
    build_kernel<<<NCLS, 256>>>(Li);
    passA_kernel<<<2080, 256, PASSA_SMEM>>>();
    passB_kernel<<<NCLS * NSLOT, 256, PASSB_SMEM>>>((float*)d_out);
}

// round 17
// speedup vs baseline: 2.9191x; 1.1998x over previous
#include <cuda_runtime.h>
#include <cuda_fp16.h>
#include <cstdint>

// SupConLoss: features [4096,2,128] f32, labels [4096] int(32|64) -> scalar f32
// N=8192. S[i,j]=dot(u'_i,u'_j), u' = normalized * (1/sqrt T).
// norm : warp-per-row normalize -> fp16; publishes labels (detects int64/int32).
// passA: single-term fp16 mma.sync, upper-tri 128x128 tiles; ns via symmetry;
//        epilogue ALSO captures positive pairs (i<j, same label) with their S.
// passC: grid-stride over captured pairs: 2S - log(ns_X+e^S) - log(ns_Y+e^S);
//        self-finalizing via completion ticket.

#define NROWS 8192
#define BQ    4096
#define RSQRT_T 3.77964473009227f   // 1/sqrt(0.07)
#define PCAP  (1 << 20)             // capture buffer (expected ~332K pairs)
#define PC_BLOCKS 296

__device__ __half g_uh[NROWS * 128];
__device__ int    g_lab[NROWS];
__device__ float  g_negsum[NROWS];
__device__ float  g_loss;
__device__ int    g_done;
__device__ int    g_pcnt;
__device__ uint2  g_pos[PCAP];      // {(i<<13)|j, bits(S)}

__device__ __forceinline__ uint32_t smem_u32(const void* p) {
    uint32_t a;
    asm("{ .reg .u64 t; cvta.to.shared.u64 t, %1; cvt.u32.u64 %0, t; }" : "=r"(a) : "l"(p));
    return a;
}

#define CP_ASYNC16(dst, src) \
    asm volatile("cp.async.ca.shared.global [%0], [%1], 16;" \
        :: "r"((uint32_t)(dst)), "l"(__cvta_generic_to_global((const void*)(src))) : "memory")
#define CP_ASYNC_COMMIT() asm volatile("cp.async.commit_group;" ::: "memory")
#define CP_ASYNC_WAIT_GROUP(n) asm volatile("cp.async.wait_group %0;" :: "n"(n) : "memory")

#define LDSM_X4(R, addr) \
    asm volatile("ldmatrix.sync.aligned.m8n8.x4.shared.b16 {%0,%1,%2,%3}, [%4];" \
        : "=r"((R)[0]), "=r"((R)[1]), "=r"((R)[2]), "=r"((R)[3]) : "r"(addr))

#define MMA16816(D, A, B0, B1) \
    asm volatile("mma.sync.aligned.m16n8k16.row.col.f32.f16.f16.f32 " \
        "{%0,%1,%2,%3}, {%4,%5,%6,%7}, {%8,%9}, {%0,%1,%2,%3};" \
        : "+f"((D)[0]), "+f"((D)[1]), "+f"((D)[2]), "+f"((D)[3]) \
        : "r"((A)[0]), "r"((A)[1]), "r"((A)[2]), "r"((A)[3]), "r"(B0), "r"(B1))

// ---------------------------------------------------------------- normalize + labels
__global__ __launch_bounds__(256) void norm_kernel(const float* __restrict__ F,
                                                   const int* __restrict__ Li) {
    __shared__ int s_nz;
    const int tid = threadIdx.x;
    if (tid == 0) s_nz = 0;
    __syncthreads();
    for (int i = tid; i < 2048; i += 256)
        if (Li[2 * i + 1] != 0) s_nz = 1;
    __syncthreads();
    const bool is64 = (s_nz == 0);

    const int w    = (blockIdx.x * 256 + tid) >> 5;   // global warp = row
    const int lane = tid & 31;
    const int b = w & (BQ - 1), v = w >> 12;

    float4 f = *(const float4*)(F + b * 256 + v * 128 + lane * 4);
    float ss = f.x * f.x + f.y * f.y + f.z * f.z + f.w * f.w;
    #pragma unroll
    for (int o = 16; o > 0; o >>= 1)
        ss += __shfl_xor_sync(0xffffffffu, ss, o);
    const float s = rsqrtf(ss) * RSQRT_T;

    __half2 h01 = __floats2half2_rn(f.x * s, f.y * s);
    __half2 h23 = __floats2half2_rn(f.z * s, f.w * s);
    uint2 hp;
    hp.x = *(uint32_t*)&h01;
    hp.y = *(uint32_t*)&h23;
    *(uint2*)(g_uh + w * 128 + lane * 4) = hp;

    if (lane == 0) {
        g_lab[w]    = is64 ? Li[2 * b] : Li[b];
        g_negsum[w] = 0.f;
        if (w == 0) { g_loss = 0.f; g_done = 0; g_pcnt = 0; }
    }
}

// ---------------------------------------------------------------- pass A
// 2 panel slots of 128 rows x 128 halves (272B stride)
#define PAN   34816u
#define O_S0  0u
#define O_S1  34816u
#define O_LAB 69632u
#define O_RED 70656u
#define PASSA_SMEM 71680

__device__ __forceinline__ void load_panel(uint32_t sa, uint32_t slot, int tid,
                                           const __half* src, int rbase) {
    #pragma unroll
    for (int t = 0; t < 8; t++) {
        int f = tid + t * 256;
        int r = f >> 4, c = f & 15;
        CP_ASYNC16(sa + slot + r * 272 + c * 16,
                   (const char*)(src + (rbase + r) * 128) + c * 16);
    }
}

__global__ __launch_bounds__(256, 2) void passA_kernel() {
    extern __shared__ char sm[];
    const uint32_t sa = smem_u32(sm);
    const int tid = threadIdx.x, wid = tid >> 5, lane = tid & 31;

    // upper-triangle tile index (64x64 tiles)
    int rem = blockIdx.x, ti = 0;
    while (rem >= 64 - ti) { rem -= 64 - ti; ti++; }
    const int tj = ti + rem;
    const int i0 = ti * 128, j0 = tj * 128;
    const bool diag = (ti == tj);

    int*   li_s  = (int*)(sm + O_LAB);
    int*   lj_s  = li_s + 128;
    float* s_row = (float*)(sm + O_RED);
    float* s_col = s_row + 128;

    ((float*)(sm + O_RED))[tid] = 0.f;
    if (tid < 128) { li_s[tid] = g_lab[i0 + tid]; lj_s[tid] = g_lab[j0 + tid]; }

    // panel fill (B aliases A on the diagonal)
    load_panel(sa, O_S0, tid, g_uh, i0);
    if (!diag) load_panel(sa, O_S1, tid, g_uh, j0);
    CP_ASYNC_COMMIT();
    CP_ASYNC_WAIT_GROUP(0);
    __syncthreads();

    // 8 warps: 4x2 grid, each warp 32x64 output
    const int wm = (wid >> 1) * 32;
    const int wn = (wid & 1) * 64;
    const int lrow = (lane & 7) + ((lane >> 3) & 1) * 8;
    const int lk   = (lane >> 4) * 8;
    const uint32_t aBase = sa + O_S0 + (uint32_t)((wm + lrow) * 272 + lk * 2);
    const uint32_t bBase = sa + (diag ? O_S0 : O_S1) + (uint32_t)((wn + lrow) * 272 + lk * 2);

    float d[2][8][4];
    #pragma unroll
    for (int a = 0; a < 2; a++)
        #pragma unroll
        for (int b = 0; b < 8; b++)
            #pragma unroll
            for (int c = 0; c < 4; c++) d[a][b][c] = 0.f;

    #pragma unroll
    for (int kk = 0; kk < 8; kk++) {
        uint32_t A[2][4], B[4][4];
        #pragma unroll
        for (int ma = 0; ma < 2; ma++)
            LDSM_X4(A[ma], aBase + kk * 32 + ma * 16 * 272);
        #pragma unroll
        for (int g = 0; g < 4; g++)
            LDSM_X4(B[g], bBase + kk * 32 + g * 16 * 272);
        #pragma unroll
        for (int ma = 0; ma < 2; ma++)
            #pragma unroll
            for (int nb = 0; nb < 8; nb++) {
                const int g = nb >> 1, h = nb & 1;
                MMA16816(d[ma][nb], A[ma], B[g][h], B[g][h + 2]);
            }
    }

    // ---- fused epilogue: masked exp, row/col sums, positive-pair count ----
    const int grp = lane >> 2, q = lane & 3;
    float rs[2][2];
    rs[0][0] = rs[0][1] = rs[1][0] = rs[1][1] = 0.f;
    float cs[8][2];
    #pragma unroll
    for (int nb = 0; nb < 8; nb++) cs[nb][0] = cs[nb][1] = 0.f;
    int cap = 0;

    #pragma unroll
    for (int ma = 0; ma < 2; ma++) {
        const int r0 = wm + ma * 16 + grp, r1 = r0 + 8;
        const int l0 = li_s[r0], l1 = li_s[r1];
        const int gi0 = i0 + r0, gi1 = i0 + r1;
        #pragma unroll
        for (int nb = 0; nb < 8; nb++) {
            const int c0 = wn + nb * 8 + q * 2;
            const int lc0 = lj_s[c0], lc1 = lj_s[c0 + 1];
            const int gj0 = j0 + c0, gj1 = gj0 + 1;
            const bool p00 = (l0 == lc0), p01 = (l0 == lc1);
            const bool p10 = (l1 == lc0), p11 = (l1 == lc1);
            float v00 = p00 ? 0.f : __expf(d[ma][nb][0]);
            float v01 = p01 ? 0.f : __expf(d[ma][nb][1]);
            float v10 = p10 ? 0.f : __expf(d[ma][nb][2]);
            float v11 = p11 ? 0.f : __expf(d[ma][nb][3]);
            rs[ma][0] += v00 + v01;
            rs[ma][1] += v10 + v11;
            cs[nb][0] += v00 + v10;
            cs[nb][1] += v01 + v11;
            cap += (p00 && gi0 < gj0) + (p01 && gi0 < gj1)
                 + (p10 && gi1 < gj0) + (p11 && gi1 < gj1);
        }
    }

    // positive-pair write: warp prefix + one atomic per warp
    {
        int pre = cap;
        #pragma unroll
        for (int o = 1; o < 32; o <<= 1) {
            int t = __shfl_up_sync(0xffffffffu, pre, o);
            if (lane >= o) pre += t;
        }
        int wtot = __shfl_sync(0xffffffffu, pre, 31);
        int wbase = 0;
        if (lane == 31 && wtot > 0) wbase = atomicAdd(&g_pcnt, wtot);
        wbase = __shfl_sync(0xffffffffu, wbase, 31);
        if (cap > 0) {
            int off = wbase + pre - cap;
            #pragma unroll
            for (int ma = 0; ma < 2; ma++) {
                const int r0 = wm + ma * 16 + grp, r1 = r0 + 8;
                const int l0 = li_s[r0], l1 = li_s[r1];
                const int gi0 = i0 + r0, gi1 = i0 + r1;
                #pragma unroll
                for (int nb = 0; nb < 8; nb++) {
                    const int c0 = wn + nb * 8 + q * 2;
                    const int lc0 = lj_s[c0], lc1 = lj_s[c0 + 1];
                    const int gj0 = j0 + c0, gj1 = gj0 + 1;
                    if (l0 == lc0 && gi0 < gj0 && off < PCAP)
                        g_pos[off++] = make_uint2((gi0 << 13) | gj0, __float_as_uint(d[ma][nb][0]));
                    if (l0 == lc1 && gi0 < gj1 && off < PCAP)
                        g_pos[off++] = make_uint2((gi0 << 13) | gj1, __float_as_uint(d[ma][nb][1]));
                    if (l1 == lc0 && gi1 < gj0 && off < PCAP)
                        g_pos[off++] = make_uint2((gi1 << 13) | gj0, __float_as_uint(d[ma][nb][2]));
                    if (l1 == lc1 && gi1 < gj1 && off < PCAP)
                        g_pos[off++] = make_uint2((gi1 << 13) | gj1, __float_as_uint(d[ma][nb][3]));
                }
            }
        }
    }

    #pragma unroll
    for (int o = 1; o <= 2; o <<= 1) {
        #pragma unroll
        for (int ma = 0; ma < 2; ma++) {
            rs[ma][0] += __shfl_xor_sync(0xffffffffu, rs[ma][0], o);
            rs[ma][1] += __shfl_xor_sync(0xffffffffu, rs[ma][1], o);
        }
    }
    if (q == 0) {
        #pragma unroll
        for (int ma = 0; ma < 2; ma++) {
            atomicAdd(&s_row[wm + ma * 16 + grp],     rs[ma][0]);
            atomicAdd(&s_row[wm + ma * 16 + grp + 8], rs[ma][1]);
        }
    }

    #pragma unroll
    for (int o = 4; o <= 16; o <<= 1)
        #pragma unroll
        for (int nb = 0; nb < 8; nb++) {
            cs[nb][0] += __shfl_xor_sync(0xffffffffu, cs[nb][0], o);
            cs[nb][1] += __shfl_xor_sync(0xffffffffu, cs[nb][1], o);
        }
    if (grp == 0) {
        #pragma unroll
        for (int nb = 0; nb < 8; nb++) {
            atomicAdd(&s_col[wn + nb * 8 + q * 2],     cs[nb][0]);
            atomicAdd(&s_col[wn + nb * 8 + q * 2 + 1], cs[nb][1]);
        }
    }
    __syncthreads();

    if (tid < 128) {
        atomicAdd(&g_negsum[j0 + tid], s_col[tid]);
        if (!diag) atomicAdd(&g_negsum[i0 + tid], s_row[tid]);
    }
}

// ---------------------------------------------------------------- pass C: pair terms + finalize
__global__ __launch_bounds__(256) void passC_kernel(float* __restrict__ out) {
    const int tid = threadIdx.x, lane = tid & 31, wid = tid >> 5;
    const int M = min(g_pcnt, PCAP);

    float acc = 0.f;
    for (int e = blockIdx.x * 256 + tid; e < M; e += PC_BLOCKS * 256) {
        uint2 pr = g_pos[e];
        const int X = pr.x >> 13, Y = pr.x & 8191;
        const float S = __uint_as_float(pr.y);
        const float ee = __expf(S);
        acc += 2.f * S - __logf(g_negsum[X] + ee) - __logf(g_negsum[Y] + ee);
    }

    #pragma unroll
    for (int o = 16; o > 0; o >>= 1)
        acc += __shfl_xor_sync(0xffffffffu, acc, o);
    __shared__ float red[8];
    if (lane == 0) red[wid] = acc;
    __syncthreads();
    if (tid == 0) {
        float s = 0.f;
        #pragma unroll
        for (int w = 0; w < 8; w++) s += red[w];
        atomicAdd(&g_loss, s);
        __threadfence();
        int old = atomicAdd(&g_done, 1);
        if (old == PC_BLOCKS - 1) {
            __threadfence();
            out[0] = -g_loss / (float)NROWS;
        }
    }
}

// ----------------------------------------------------------------
extern "C" void kernel_launch(void* const* d_in, const int* in_sizes, int n_in,
                              void* d_out, int out_size) {
    const float* F  = (const float*)d_in[0];
    const int*   Li = (const int*)d_in[1];

    cudaFuncSetAttribute(passA_kernel, cudaFuncAttributeMaxDynamicSharedMemorySize, PASSA_SMEM);

    norm_kernel<<<NROWS / 8, 256>>>(F, Li);
    passA_kernel<<<2080, 256, PASSA_SMEM>>>();
    passC_kernel<<<PC_BLOCKS, 256>>>((float*)d_out);
}